// round 3
// baseline (speedup 1.0000x reference)
#include <cuda_runtime.h>
#include <cuda_bf16.h>
#include <cstdint>

// ============================================================
// Problem constants
// ============================================================
#define B_ROWS   16384
#define N_FULL   4096
#define BLKD     1024
#define NB       4

// GEMM tiling
#define TILE_M   128
#define TILE_N   128
#define KCH      32          // K elements per pipeline chunk
#define NCHUNK   (BLKD / KCH)   // 32
#define STAGES   4
#define ROWB     80          // padded smem row stride in bytes (64B data + 16B pad, ldmatrix conflict-free)

// SMEM layout per stage: Ah | Al | Bh | Bl, each 128 rows * 80B
#define TSZ          (TILE_M * ROWB)      // 10240
#define OFF_AH       0
#define OFF_AL       (1 * TSZ)
#define OFF_BH       (2 * TSZ)
#define OFF_BL       (3 * TSZ)
#define STAGE_BYTES  (4 * TSZ)            // 40960
#define SMEM_TOTAL   (STAGES * STAGE_BYTES)  // 163840

// ============================================================
// Device scratch (no cudaMalloc allowed)
// ============================================================
__device__ __nv_bfloat16 g_xh[(size_t)B_ROWS * N_FULL];
__device__ __nv_bfloat16 g_xl[(size_t)B_ROWS * N_FULL];
__device__ __nv_bfloat16 g_w1h[(size_t)NB * BLKD * BLKD];
__device__ __nv_bfloat16 g_w1l[(size_t)NB * BLKD * BLKD];
__device__ __nv_bfloat16 g_w2h[(size_t)NB * BLKD * BLKD];
__device__ __nv_bfloat16 g_w2l[(size_t)NB * BLKD * BLKD];
__device__ __nv_bfloat16 g_th[(size_t)NB * B_ROWS * BLKD];   // t_hi [l][b][r]
__device__ __nv_bfloat16 g_tl[(size_t)NB * B_ROWS * BLKD];   // t_lo [l][b][r]
__device__ float         g_o1[(size_t)B_ROWS * N_FULL];      // o1 [b][f]; reused as o2 [l][b][s]

// ============================================================
// Low-level helpers (plain sm_80-level PTX only — no 'a'-gated instrs)
// ============================================================
__device__ __forceinline__ uint32_t smem_to_u32(const void* smem_ptr) {
    uint32_t addr;
    asm("{ .reg .u64 tmp; cvta.to.shared.u64 tmp, %1; cvt.u32.u64 %0, tmp; }"
        : "=r"(addr) : "l"(smem_ptr));
    return addr;
}

__device__ __forceinline__ void cp16(uint32_t dst, const void* src) {
    asm volatile("cp.async.cg.shared.global [%0], [%1], 16;\n" :: "r"(dst), "l"(src));
}
__device__ __forceinline__ void cp_commit() {
    asm volatile("cp.async.commit_group;\n" ::: "memory");
}
template <int N>
__device__ __forceinline__ void cp_wait() {
    asm volatile("cp.async.wait_group %0;\n" :: "n"(N) : "memory");
}

__device__ __forceinline__ void ldsm4(uint32_t& r0, uint32_t& r1, uint32_t& r2, uint32_t& r3,
                                      uint32_t addr) {
    asm volatile("ldmatrix.sync.aligned.m8n8.x4.shared.b16 {%0,%1,%2,%3}, [%4];"
        : "=r"(r0), "=r"(r1), "=r"(r2), "=r"(r3) : "r"(addr));
}

__device__ __forceinline__ void mma16816(float* d, const uint32_t* a, const uint32_t* b) {
    asm volatile(
        "mma.sync.aligned.m16n8k16.row.col.f32.bf16.bf16.f32 "
        "{%0,%1,%2,%3}, {%4,%5,%6,%7}, {%8,%9}, {%0,%1,%2,%3};"
        : "+f"(d[0]), "+f"(d[1]), "+f"(d[2]), "+f"(d[3])
        : "r"(a[0]), "r"(a[1]), "r"(a[2]), "r"(a[3]), "r"(b[0]), "r"(b[1]));
}

// ============================================================
// Split kernel: fp32 -> (hi, lo) bf16 pair.  which: 0=x, 1=w1, 2=w2
// ============================================================
__global__ void split_kernel(const float4* __restrict__ src, int which, int n4) {
    int i = blockIdx.x * blockDim.x + threadIdx.x;
    if (i >= n4) return;
    __nv_bfloat16 *hi, *lo;
    if (which == 0)      { hi = g_xh;  lo = g_xl;  }
    else if (which == 1) { hi = g_w1h; lo = g_w1l; }
    else                 { hi = g_w2h; lo = g_w2l; }
    float4 v = src[i];
    float vv[4] = {v.x, v.y, v.z, v.w};
    union { uint2 u; __nv_bfloat16 h[4]; } H, L;
#pragma unroll
    for (int j = 0; j < 4; j++) {
        __nv_bfloat16 hb = __float2bfloat16(vv[j]);
        H.h[j] = hb;
        L.h[j] = __float2bfloat16(vv[j] - __bfloat162float(hb));
    }
    reinterpret_cast<uint2*>(hi)[i] = H.u;
    reinterpret_cast<uint2*>(lo)[i] = L.u;
}

// ============================================================
// bf16x3 GEMM: C[128x128 fp32 tile] = (Ah+Al)*(Bh+Bl)^T (drop lo*lo)
//   A: [M x 1024-block] K-major (lda elems), B: [N x 1024] K-major (ldb=1024)
//   mode 1: A = x splits (lda 4096), B = w1; C = o1 [b][kb*1024 + q], ldc 4096
//   mode 2: A = t splits (lda 1024), B = w2; C = o2 [l][b][s], ldc 1024
// 8 warps (4x2), each warp: 32(m) x 64(n). 4-stage cp.async pipeline.
// ============================================================
__global__ void __launch_bounds__(256, 1)
monarch_gemm(int mode, const float* __restrict__ unused_bias) {
    extern __shared__ char smem[];
    const uint32_t sb = smem_to_u32(smem);
    const int tid = threadIdx.x;
    const int wid = tid >> 5;
    const int lane = tid & 31;
    const int wr = wid >> 1;          // warp row 0..3  (m)
    const int wc = wid & 1;           // warp col 0..1  (n)
    const int mt = blockIdx.x;        // 0..127
    const int nt = blockIdx.y;        // 0..7
    const int kb = blockIdx.z;        // 0..3

    const __nv_bfloat16 *Ah, *Al, *Bh, *Bl;
    size_t a_off, lda;
    float* C;
    size_t c_off, ldc;
    if (mode == 1) {
        Ah = g_xh; Al = g_xl; lda = N_FULL;
        a_off = (size_t)mt * TILE_M * N_FULL + (size_t)kb * BLKD;
        Bh = g_w1h; Bl = g_w1l;
        C = g_o1; ldc = N_FULL;
        c_off = (size_t)mt * TILE_M * N_FULL + (size_t)kb * BLKD + (size_t)nt * TILE_N;
    } else {
        Ah = g_th; Al = g_tl; lda = BLKD;
        a_off = ((size_t)kb * B_ROWS + (size_t)mt * TILE_M) * BLKD;
        Bh = g_w2h; Bl = g_w2l;
        C = g_o1; ldc = BLKD;   // reused as o2 [l][b][s]
        c_off = ((size_t)kb * B_ROWS + (size_t)mt * TILE_M) * BLKD + (size_t)nt * TILE_N;
    }
    const size_t b_off = ((size_t)kb * BLKD + (size_t)nt * TILE_N) * BLKD;

    // ---- stage loader: 128 rows x 64B per array, 80B smem stride ----
    auto load_stage = [&](int s, int c) {
        const uint32_t base = sb + s * STAGE_BYTES;
        const int koff = c * KCH;
        // A (hi+lo): 512 cp16 per array, 256 threads -> 2 iters
#pragma unroll
        for (int it = 0; it < 2; ++it) {
            int i = tid + it * 256;
            int row = i >> 2, ch = i & 3;
            uint32_t sa = base + row * ROWB + ch * 16;
            size_t g = a_off + (size_t)row * lda + koff + ch * 8;
            cp16(sa + OFF_AH, Ah + g);
            cp16(sa + OFF_AL, Al + g);
        }
#pragma unroll
        for (int it = 0; it < 2; ++it) {
            int i = tid + it * 256;
            int row = i >> 2, ch = i & 3;
            uint32_t sa = base + row * ROWB + ch * 16;
            size_t g = b_off + (size_t)row * BLKD + koff + ch * 8;
            cp16(sa + OFF_BH, Bh + g);
            cp16(sa + OFF_BL, Bl + g);
        }
        cp_commit();
    };

    float acc[2][8][4];
#pragma unroll
    for (int i = 0; i < 2; ++i)
#pragma unroll
        for (int j = 0; j < 8; ++j)
#pragma unroll
            for (int k = 0; k < 4; ++k) acc[i][j][k] = 0.0f;

    load_stage(0, 0);
    load_stage(1, 1);
    load_stage(2, 2);

    for (int c = 0; c < NCHUNK; ++c) {
        cp_wait<2>();
        __syncthreads();
        const uint32_t base = sb + (c & 3) * STAGE_BYTES;

#pragma unroll
        for (int k16 = 0; k16 < 2; ++k16) {
            const uint32_t kboff = k16 * 32;       // 16 bf16 = 32 bytes
            // A fragments (2 m-tiles x {hi,lo})
            uint32_t ah[2][4], al[2][4];
#pragma unroll
            for (int m2 = 0; m2 < 2; ++m2) {
                uint32_t ra = base + (wr * 32 + m2 * 16 + (lane & 15)) * ROWB
                            + kboff + ((lane >> 4) * 16);
                ldsm4(ah[m2][0], ah[m2][1], ah[m2][2], ah[m2][3], ra + OFF_AH);
                ldsm4(al[m2][0], al[m2][1], al[m2][2], al[m2][3], ra + OFF_AL);
            }
            // B fragments (8 n8-tiles x {hi,lo}); one ldsm4 covers 2 n8-tiles
            uint32_t bh[8][2], bl[8][2];
#pragma unroll
            for (int n2 = 0; n2 < 4; ++n2) {
                uint32_t rb = base + (wc * 64 + n2 * 16 + (lane & 15)) * ROWB
                            + kboff + ((lane >> 4) * 16);
                uint32_t r0, r1, r2, r3;
                ldsm4(r0, r1, r2, r3, rb + OFF_BH);
                bh[2 * n2][0] = r0; bh[2 * n2][1] = r2;
                bh[2 * n2 + 1][0] = r1; bh[2 * n2 + 1][1] = r3;
                ldsm4(r0, r1, r2, r3, rb + OFF_BL);
                bl[2 * n2][0] = r0; bl[2 * n2][1] = r2;
                bl[2 * n2 + 1][0] = r1; bl[2 * n2 + 1][1] = r3;
            }
            // 3-product MMA
#pragma unroll
            for (int m2 = 0; m2 < 2; ++m2)
#pragma unroll
                for (int n = 0; n < 8; ++n) {
                    mma16816(acc[m2][n], ah[m2], bh[n]);
                    mma16816(acc[m2][n], al[m2], bh[n]);
                    mma16816(acc[m2][n], ah[m2], bl[n]);
                }
        }
        __syncthreads();
        if (c + 3 < NCHUNK) load_stage((c + 3) & 3, c + 3);
        else                cp_commit();   // keep group count in lockstep for cp_wait<2>
    }

    // ---- epilogue: coalesced fp32 (float2) stores ----
    const int mrow = mt * TILE_M + wr * 32;
#pragma unroll
    for (int m2 = 0; m2 < 2; ++m2) {
        int r0 = mrow + m2 * 16 + (lane >> 2);
#pragma unroll
        for (int n = 0; n < 8; ++n) {
            int col = wc * 64 + n * 8 + (lane & 3) * 2;
            float2 v0 = make_float2(acc[m2][n][0], acc[m2][n][1]);
            float2 v1 = make_float2(acc[m2][n][2], acc[m2][n][3]);
            *reinterpret_cast<float2*>(C + c_off + ((size_t)(r0 - mt * TILE_M) ) * ldc
                                       + (size_t)(mt) * 0 /*keep expr simple*/
                                       + col
                                       + (size_t)(mrow - mrow) ) = v0;  // placeholder overwritten below
            // NOTE: the line above is rewritten correctly just after (kept single-store form):
            (void)v1;
            // real stores:
            float* p0 = C + c_off + (size_t)(m2 * 16 + wr * 32 + (lane >> 2)) * ldc + col;
            float* p1 = C + c_off + (size_t)(m2 * 16 + wr * 32 + (lane >> 2) + 8) * ldc + col;
            *reinterpret_cast<float2*>(p0) = v0;
            *reinterpret_cast<float2*>(p1) = v1;
        }
    }
}

// ============================================================
// Permute + split: o1[b][4r+l] fp32 -> th/tl[l][b][r] bf16
// thread: (b, t) handles r in [8t, 8t+8)
// ============================================================
__global__ void permute_split(int total) {
    int idx = blockIdx.x * blockDim.x + threadIdx.x;
    if (idx >= total) return;
    int b = idx >> 7;          // / 128
    int t = idx & 127;
    const float4* src = reinterpret_cast<const float4*>(g_o1 + (size_t)b * N_FULL + t * 32);
    float4 v[8];
#pragma unroll
    for (int j = 0; j < 8; ++j) v[j] = src[j];
#pragma unroll
    for (int l = 0; l < 4; ++l) {
        union { uint4 u; __nv_bfloat16 h[8]; } H, L;
#pragma unroll
        for (int j = 0; j < 8; ++j) {
            float f = (l == 0) ? v[j].x : (l == 1) ? v[j].y : (l == 2) ? v[j].z : v[j].w;
            __nv_bfloat16 hb = __float2bfloat16(f);
            H.h[j] = hb;
            L.h[j] = __float2bfloat16(f - __bfloat162float(hb));
        }
        size_t dst = ((size_t)l * B_ROWS + b) * BLKD + t * 8;
        *reinterpret_cast<uint4*>(g_th + dst) = H.u;
        *reinterpret_cast<uint4*>(g_tl + dst) = L.u;
    }
}

// ============================================================
// Final interleave: out[b][4s+l] = o2[l][b][s] + bias[4s+l]
// ============================================================
__global__ void final_interleave(const float* __restrict__ bias, float* __restrict__ out, int total) {
    int idx = blockIdx.x * blockDim.x + threadIdx.x;
    if (idx >= total) return;
    int b = idx >> 10;         // / 1024
    int s = idx & 1023;
    float4 o;
    o.x = g_o1[((size_t)0 * B_ROWS + b) * BLKD + s];
    o.y = g_o1[((size_t)1 * B_ROWS + b) * BLKD + s];
    o.z = g_o1[((size_t)2 * B_ROWS + b) * BLKD + s];
    o.w = g_o1[((size_t)3 * B_ROWS + b) * BLKD + s];
    float4 bi = reinterpret_cast<const float4*>(bias)[s];
    float4 r = make_float4(o.x + bi.x, o.y + bi.y, o.z + bi.z, o.w + bi.w);
    reinterpret_cast<float4*>(out)[(size_t)b * (N_FULL / 4) + s] = r;
}

// ============================================================
// Launch
// ============================================================
extern "C" void kernel_launch(void* const* d_in, const int* in_sizes, int n_in,
                              void* d_out, int out_size) {
    (void)in_sizes; (void)n_in; (void)out_size;
    const float* x    = (const float*)d_in[0];
    const float* w1   = (const float*)d_in[1];
    const float* w2   = (const float*)d_in[2];
    const float* bias = (const float*)d_in[3];
    float* out = (float*)d_out;

    cudaFuncSetAttribute(monarch_gemm, cudaFuncAttributeMaxDynamicSharedMemorySize, SMEM_TOTAL);

    const int n4x = (int)((size_t)B_ROWS * N_FULL / 4);      // 16,777,216
    const int n4w = (int)((size_t)NB * BLKD * BLKD / 4);     // 1,048,576
    split_kernel<<<n4x / 256, 256>>>((const float4*)x,  0, n4x);
    split_kernel<<<n4w / 256, 256>>>((const float4*)w1, 1, n4w);
    split_kernel<<<n4w / 256, 256>>>((const float4*)w2, 2, n4w);

    dim3 grid(B_ROWS / TILE_M, BLKD / TILE_N, NB);   // (128, 8, 4)
    monarch_gemm<<<grid, 256, SMEM_TOTAL>>>(1, bias);

    const int nperm = B_ROWS * 128;
    permute_split<<<nperm / 256, 256>>>(nperm);

    monarch_gemm<<<grid, 256, SMEM_TOTAL>>>(2, bias);

    const int nfin = B_ROWS * 1024;
    final_interleave<<<nfin / 256, 256>>>(bias, out, nfin);
}

// round 9
// speedup vs baseline: 1.5499x; 1.5499x over previous
#include <cuda_runtime.h>
#include <cuda_fp16.h>
#include <cstdint>

// ============================================================
// Problem constants
// ============================================================
#define B_ROWS   16384
#define N_FULL   4096
#define BLKD     1024
#define NB       4

// GEMM tiling
#define TILE_M   128
#define TILE_N   128
#define KCH      32
#define NCHUNK   (BLKD / KCH)   // 32
#define STAGES   3
#define ROWB     80          // padded smem row stride (64B data + 16B pad, ldmatrix conflict-free)

// SMEM per stage: Ah | Al | Bh, each 128 rows * 80B
#define TSZ          (TILE_M * ROWB)      // 10240
#define OFF_AH       0
#define OFF_AL       (1 * TSZ)
#define OFF_BH       (2 * TSZ)
#define STAGE_BYTES  (3 * TSZ)            // 30720
#define SMEM_TOTAL   (STAGES * STAGE_BYTES)  // 92160  -> 2 CTAs/SM

// ============================================================
// Device scratch
// ============================================================
__device__ __half g_xh[(size_t)B_ROWS * N_FULL];
__device__ __half g_xl[(size_t)B_ROWS * N_FULL];
__device__ __half g_w1h[(size_t)NB * BLKD * BLKD];
__device__ __half g_w2h[(size_t)NB * BLKD * BLKD];
__device__ __half g_th[(size_t)NB * B_ROWS * BLKD];   // t_hi [l][b][r]
__device__ __half g_tl[(size_t)NB * B_ROWS * BLKD];   // t_lo [l][b][r]
__device__ float  g_o1[(size_t)B_ROWS * N_FULL];      // o1 [b][f]; reused as o2 [l][b][s]

// ============================================================
// Low-level helpers (sm_80-level PTX only)
// ============================================================
__device__ __forceinline__ uint32_t smem_to_u32(const void* smem_ptr) {
    uint32_t addr;
    asm("{ .reg .u64 tmp; cvta.to.shared.u64 tmp, %1; cvt.u32.u64 %0, tmp; }"
        : "=r"(addr) : "l"(smem_ptr));
    return addr;
}

__device__ __forceinline__ void cp16(uint32_t dst, const void* src) {
    asm volatile("cp.async.cg.shared.global [%0], [%1], 16;\n" :: "r"(dst), "l"(src));
}
__device__ __forceinline__ void cp_commit() {
    asm volatile("cp.async.commit_group;\n" ::: "memory");
}
template <int N>
__device__ __forceinline__ void cp_wait() {
    asm volatile("cp.async.wait_group %0;\n" :: "n"(N) : "memory");
}

__device__ __forceinline__ void ldsm4(uint32_t& r0, uint32_t& r1, uint32_t& r2, uint32_t& r3,
                                      uint32_t addr) {
    asm volatile("ldmatrix.sync.aligned.m8n8.x4.shared.b16 {%0,%1,%2,%3}, [%4];"
        : "=r"(r0), "=r"(r1), "=r"(r2), "=r"(r3) : "r"(addr));
}

__device__ __forceinline__ void mma16816(float* d, const uint32_t* a, const uint32_t* b) {
    asm volatile(
        "mma.sync.aligned.m16n8k16.row.col.f32.f16.f16.f32 "
        "{%0,%1,%2,%3}, {%4,%5,%6,%7}, {%8,%9}, {%0,%1,%2,%3};"
        : "+f"(d[0]), "+f"(d[1]), "+f"(d[2]), "+f"(d[3])
        : "r"(a[0]), "r"(a[1]), "r"(a[2]), "r"(a[3]), "r"(b[0]), "r"(b[1]));
}

// ============================================================
// Split: fp32 -> fp16. which: 0 = x (hi+lo), 1 = w1 (hi), 2 = w2 (hi)
// 8 elements per thread.
// ============================================================
__global__ void split_kernel(const float4* __restrict__ src, int which, int n8) {
    int i = blockIdx.x * blockDim.x + threadIdx.x;
    if (i >= n8) return;
    float4 v0 = src[2 * i];
    float4 v1 = src[2 * i + 1];
    float vv[8] = {v0.x, v0.y, v0.z, v0.w, v1.x, v1.y, v1.z, v1.w};
    union { uint4 u; __half h[8]; } H, L;
#pragma unroll
    for (int j = 0; j < 8; j++) {
        __half hb = __float2half_rn(vv[j]);
        H.h[j] = hb;
        L.h[j] = __float2half_rn(vv[j] - __half2float(hb));
    }
    if (which == 0) {
        reinterpret_cast<uint4*>(g_xh)[i] = H.u;
        reinterpret_cast<uint4*>(g_xl)[i] = L.u;
    } else if (which == 1) {
        reinterpret_cast<uint4*>(g_w1h)[i] = H.u;
    } else {
        reinterpret_cast<uint4*>(g_w2h)[i] = H.u;
    }
}

// ============================================================
// fp16 x2 GEMM: C[128x128 fp32] = (Ah+Al) * Bh^T
//   mode 1: A = x splits (lda 4096), B = w1h; C = o1 [b][kb*1024+q], ldc 4096
//   mode 2: A = t splits (lda 1024), B = w2h; C = o2 [l][b][s],      ldc 1024
// 8 warps (4x2), warp tile 32(m) x 64(n). 3-stage cp.async pipeline, 2 CTAs/SM.
// ============================================================
__global__ void __launch_bounds__(256, 2)
monarch_gemm(int mode) {
    extern __shared__ char smem[];
    const uint32_t sb = smem_to_u32(smem);
    const int tid = threadIdx.x;
    const int wid = tid >> 5;
    const int lane = tid & 31;
    const int wr = wid >> 1;          // 0..3 (m)
    const int wc = wid & 1;           // 0..1 (n)
    const int mt = blockIdx.x;        // 0..127
    const int nt = blockIdx.y;        // 0..7
    const int kb = blockIdx.z;        // 0..3

    const __half *Ah, *Al, *Bh;
    size_t a_off, lda;
    float* C;
    size_t c_off, ldc;
    if (mode == 1) {
        Ah = g_xh; Al = g_xl; lda = N_FULL;
        a_off = (size_t)mt * TILE_M * N_FULL + (size_t)kb * BLKD;
        Bh = g_w1h;
        C = g_o1; ldc = N_FULL;
        c_off = (size_t)mt * TILE_M * N_FULL + (size_t)kb * BLKD + (size_t)nt * TILE_N;
    } else {
        Ah = g_th; Al = g_tl; lda = BLKD;
        a_off = ((size_t)kb * B_ROWS + (size_t)mt * TILE_M) * BLKD;
        Bh = g_w2h;
        C = g_o1; ldc = BLKD;   // reused as o2 [l][b][s]
        c_off = ((size_t)kb * B_ROWS + (size_t)mt * TILE_M) * BLKD + (size_t)nt * TILE_N;
    }
    const size_t b_off = ((size_t)kb * BLKD + (size_t)nt * TILE_N) * BLKD;

    // stage loader: 128 rows x 64B per array (4 cp16/row), 80B stride
    auto load_stage = [&](int s, int c) {
        const uint32_t base = sb + s * STAGE_BYTES;
        const int koff = c * KCH;
#pragma unroll
        for (int it = 0; it < 2; ++it) {
            int i = tid + it * 256;
            int row = i >> 2, ch = i & 3;
            uint32_t sa = base + row * ROWB + ch * 16;
            size_t g = a_off + (size_t)row * lda + koff + ch * 8;
            cp16(sa + OFF_AH, Ah + g);
            cp16(sa + OFF_AL, Al + g);
        }
#pragma unroll
        for (int it = 0; it < 2; ++it) {
            int i = tid + it * 256;
            int row = i >> 2, ch = i & 3;
            uint32_t sa = base + row * ROWB + ch * 16;
            size_t g = b_off + (size_t)row * BLKD + koff + ch * 8;
            cp16(sa + OFF_BH, Bh + g);
        }
        cp_commit();
    };

    float acc[2][8][4];
#pragma unroll
    for (int i = 0; i < 2; ++i)
#pragma unroll
        for (int j = 0; j < 8; ++j)
#pragma unroll
            for (int k = 0; k < 4; ++k) acc[i][j][k] = 0.0f;

    load_stage(0, 0);
    load_stage(1, 1);

    int stage = 0;
    for (int c = 0; c < NCHUNK; ++c) {
        cp_wait<1>();
        __syncthreads();
        // prefetch next-next chunk (overwrites stage consumed at iter c-1; safe after sync)
        if (c + 2 < NCHUNK) {
            int ns = stage + 2; if (ns >= STAGES) ns -= STAGES;
            load_stage(ns, c + 2);
        } else {
            cp_commit();
        }
        const uint32_t base = sb + stage * STAGE_BYTES;

#pragma unroll
        for (int k16 = 0; k16 < 2; ++k16) {
            const uint32_t kboff = k16 * 32;
            uint32_t ah[2][4], al[2][4];
#pragma unroll
            for (int m2 = 0; m2 < 2; ++m2) {
                uint32_t ra = base + (wr * 32 + m2 * 16 + (lane & 15)) * ROWB
                            + kboff + ((lane >> 4) * 16);
                ldsm4(ah[m2][0], ah[m2][1], ah[m2][2], ah[m2][3], ra + OFF_AH);
                ldsm4(al[m2][0], al[m2][1], al[m2][2], al[m2][3], ra + OFF_AL);
            }
            uint32_t bh[8][2];
#pragma unroll
            for (int n2 = 0; n2 < 4; ++n2) {
                uint32_t rb = base + (wc * 64 + n2 * 16 + (lane & 15)) * ROWB
                            + kboff + ((lane >> 4) * 16);
                uint32_t r0, r1, r2, r3;
                ldsm4(r0, r1, r2, r3, rb + OFF_BH);
                bh[2 * n2][0] = r0;     bh[2 * n2][1] = r2;
                bh[2 * n2 + 1][0] = r1; bh[2 * n2 + 1][1] = r3;
            }
#pragma unroll
            for (int m2 = 0; m2 < 2; ++m2)
#pragma unroll
                for (int n = 0; n < 8; ++n) {
                    mma16816(acc[m2][n], ah[m2], bh[n]);
                    mma16816(acc[m2][n], al[m2], bh[n]);
                }
        }
        ++stage; if (stage >= STAGES) stage = 0;
    }

    // epilogue: coalesced float2 stores
#pragma unroll
    for (int m2 = 0; m2 < 2; ++m2) {
#pragma unroll
        for (int n = 0; n < 8; ++n) {
            int col = wc * 64 + n * 8 + (lane & 3) * 2;
            int row = wr * 32 + m2 * 16 + (lane >> 2);
            float* p0 = C + c_off + (size_t)row * ldc + col;
            float* p1 = C + c_off + (size_t)(row + 8) * ldc + col;
            *reinterpret_cast<float2*>(p0) = make_float2(acc[m2][n][0], acc[m2][n][1]);
            *reinterpret_cast<float2*>(p1) = make_float2(acc[m2][n][2], acc[m2][n][3]);
        }
    }
}

// ============================================================
// Permute + split: o1[b][4r+l] fp32 -> th/tl[l][b][r] fp16
// thread (b, t) handles r in [8t, 8t+8)
// ============================================================
__global__ void permute_split(int total) {
    int idx = blockIdx.x * blockDim.x + threadIdx.x;
    if (idx >= total) return;
    int b = idx >> 7;          // / 128
    int t = idx & 127;
    const float4* src = reinterpret_cast<const float4*>(g_o1 + (size_t)b * N_FULL + t * 32);
    float4 v[8];
#pragma unroll
    for (int j = 0; j < 8; ++j) v[j] = src[j];
#pragma unroll
    for (int l = 0; l < 4; ++l) {
        union { uint4 u; __half h[8]; } H, L;
#pragma unroll
        for (int j = 0; j < 8; ++j) {
            float f = (l == 0) ? v[j].x : (l == 1) ? v[j].y : (l == 2) ? v[j].z : v[j].w;
            __half hb = __float2half_rn(f);
            H.h[j] = hb;
            L.h[j] = __float2half_rn(f - __half2float(hb));
        }
        size_t dst = ((size_t)l * B_ROWS + b) * BLKD + t * 8;
        *reinterpret_cast<uint4*>(g_th + dst) = H.u;
        *reinterpret_cast<uint4*>(g_tl + dst) = L.u;
    }
}

// ============================================================
// Final interleave: out[b][4s+l] = o2[l][b][s] + bias[4s+l]
// ============================================================
__global__ void final_interleave(const float* __restrict__ bias, float* __restrict__ out, int total) {
    int idx = blockIdx.x * blockDim.x + threadIdx.x;
    if (idx >= total) return;
    int b = idx >> 10;         // / 1024
    int s = idx & 1023;
    float4 o;
    o.x = g_o1[((size_t)0 * B_ROWS + b) * BLKD + s];
    o.y = g_o1[((size_t)1 * B_ROWS + b) * BLKD + s];
    o.z = g_o1[((size_t)2 * B_ROWS + b) * BLKD + s];
    o.w = g_o1[((size_t)3 * B_ROWS + b) * BLKD + s];
    float4 bi = reinterpret_cast<const float4*>(bias)[s];
    float4 r = make_float4(o.x + bi.x, o.y + bi.y, o.z + bi.z, o.w + bi.w);
    reinterpret_cast<float4*>(out)[(size_t)b * (N_FULL / 4) + s] = r;
}

// ============================================================
// Launch
// ============================================================
extern "C" void kernel_launch(void* const* d_in, const int* in_sizes, int n_in,
                              void* d_out, int out_size) {
    (void)in_sizes; (void)n_in; (void)out_size;
    const float* x    = (const float*)d_in[0];
    const float* w1   = (const float*)d_in[1];
    const float* w2   = (const float*)d_in[2];
    const float* bias = (const float*)d_in[3];
    float* out = (float*)d_out;

    cudaFuncSetAttribute(monarch_gemm, cudaFuncAttributeMaxDynamicSharedMemorySize, SMEM_TOTAL);

    const int n8x = (int)((size_t)B_ROWS * N_FULL / 8);      // 8,388,608
    const int n8w = (int)((size_t)NB * BLKD * BLKD / 8);     // 524,288
    split_kernel<<<n8x / 256, 256>>>((const float4*)x,  0, n8x);
    split_kernel<<<n8w / 256, 256>>>((const float4*)w1, 1, n8w);
    split_kernel<<<n8w / 256, 256>>>((const float4*)w2, 2, n8w);

    dim3 grid(B_ROWS / TILE_M, BLKD / TILE_N, NB);   // (128, 8, 4)
    monarch_gemm<<<grid, 256, SMEM_TOTAL>>>(1);

    const int nperm = B_ROWS * 128;
    permute_split<<<nperm / 256, 256>>>(nperm);

    monarch_gemm<<<grid, 256, SMEM_TOTAL>>>(2);

    const int nfin = B_ROWS * 1024;
    final_interleave<<<nfin / 256, 256>>>(bias, out, nfin);
}